// round 6
// baseline (speedup 1.0000x reference)
#include <cuda_runtime.h>
#include <math.h>

#define B 65536
#define N 512
#define EPSF 1e-8f
#define BLOCKS1 1024
#define BLOCKS2 1024
#define RPW 8   // rows per warp (8 warps/block)

// ---------------- scratch (device globals; no allocation allowed) ----------
__device__ __align__(16) float  g_sim[B];              // 256 KB
__device__ __align__(8)  float2 g_rowstat[B];          // 512 KB: (rowmax, 1/rowsum) of anchors
__device__ float g_colpart[BLOCKS1 * N];               // 2 MB: per-pass1-block column sums
__device__ float g_colsum[N];
__device__ float g_thirdpart[BLOCKS2];
__device__ float g_clpart[BLOCKS2];
__device__ float g_sopart[BLOCKS2];
__device__ unsigned int g_count = 0;

__device__ __forceinline__ float warp_max(float v) {
#pragma unroll
    for (int o = 16; o; o >>= 1) v = fmaxf(v, __shfl_xor_sync(0xffffffffu, v, o));
    return v;
}

// ---------------------------------------------------------------------------
// Pass 1: per-row softmax of anchors & neighbors, sim[row], rowstat[row],
// and per-block column partial sums of anchors_prob (register-accumulated).
// grid = 1024 blocks x 256 threads; 1 warp per row, 8 rows per warp.
// ---------------------------------------------------------------------------
__global__ void __launch_bounds__(256, 4) pass1_kernel(const float* __restrict__ A,
                                                       const float* __restrict__ Nb) {
    const int warp = threadIdx.x >> 5;
    const int lane = threadIdx.x & 31;
    const int base = (blockIdx.x * 8 + warp) * RPW;

    float colacc[16];
#pragma unroll
    for (int i = 0; i < 16; i++) colacc[i] = 0.f;

    for (int r = 0; r < RPW; r++) {
        const int row = base + r;
        const float4* a4 = reinterpret_cast<const float4*>(A  + (size_t)row * N) + lane;
        const float4* n4 = reinterpret_cast<const float4*>(Nb + (size_t)row * N) + lane;

        float a[16], bb[16];
#pragma unroll
        for (int c = 0; c < 4; c++) {
            float4 t = a4[c * 32];
            a[4*c+0] = t.x; a[4*c+1] = t.y; a[4*c+2] = t.z; a[4*c+3] = t.w;
            float4 u = n4[c * 32];
            bb[4*c+0] = u.x; bb[4*c+1] = u.y; bb[4*c+2] = u.z; bb[4*c+3] = u.w;
        }

        float ma = -1e30f, mn = -1e30f;
#pragma unroll
        for (int i = 0; i < 16; i++) { ma = fmaxf(ma, a[i]); mn = fmaxf(mn, bb[i]); }
        ma = warp_max(ma);
        mn = warp_max(mn);

        float sa = 0.f, sb = 0.f, sd = 0.f;
#pragma unroll
        for (int i = 0; i < 16; i++) {
            a[i] = __expf(a[i] - ma);
            float e = __expf(bb[i] - mn);
            sa += a[i]; sb += e; sd += a[i] * e;
        }
#pragma unroll
        for (int o = 16; o; o >>= 1) {
            sa += __shfl_xor_sync(0xffffffffu, sa, o);
            sb += __shfl_xor_sync(0xffffffffu, sb, o);
            sd += __shfl_xor_sync(0xffffffffu, sd, o);
        }

        const float inv = 1.f / sa;
        if (lane == 0) {
            g_sim[row] = sd / (sa * sb);
            g_rowstat[row] = make_float2(ma, inv);
        }
#pragma unroll
        for (int i = 0; i < 16; i++) colacc[i] += a[i] * inv;
    }

    // combine per-warp register accumulators once
    __shared__ float scol[8][N];                 // 16 KB
#pragma unroll
    for (int c = 0; c < 4; c++) {
        *reinterpret_cast<float4*>(&scol[warp][c * 128 + 4 * lane]) =
            make_float4(colacc[4*c+0], colacc[4*c+1], colacc[4*c+2], colacc[4*c+3]);
    }
    __syncthreads();

    for (int col = threadIdx.x; col < N; col += 256) {
        float s = 0.f;
#pragma unroll
        for (int w = 0; w < 8; w++) s += scol[w][col];
        g_colpart[(size_t)blockIdx.x * N + col] = s;
    }
}

// ---------------------------------------------------------------------------
// Pass 2: third-order term using stored rowstats (no max/sum recompute),
// plus distributed reductions of sim (consistency/second-order) and colpart,
// plus final combine in the last-finishing block.
// grid = 1024 blocks x 256 threads.
// ---------------------------------------------------------------------------
__device__ __forceinline__ float block_sum_256(float v, float* sh) {
    const int tid = threadIdx.x;
    sh[tid] = v; __syncthreads();
#pragma unroll
    for (int st = 128; st > 0; st >>= 1) {
        if (tid < st) sh[tid] += sh[tid + st];
        __syncthreads();
    }
    float r = sh[0]; __syncthreads();
    return r;
}

__global__ void __launch_bounds__(256) pass2_kernel(const float* __restrict__ A,
                                                    float* __restrict__ out) {
    const int warp = threadIdx.x >> 5;
    const int lane = threadIdx.x & 31;
    const int tid  = threadIdx.x;
    const int base = (blockIdx.x * 8 + warp) * RPW;

    float acc = 0.f;
    for (int r = 0; r < RPW; r++) {
        const int row = base + r;
        const float4* a4 = reinterpret_cast<const float4*>(A + (size_t)row * N) + lane;
        const float4* s4 = reinterpret_cast<const float4*>(g_sim + ((row & 127) << 9)) + lane;

        float a[16], sv[16];
#pragma unroll
        for (int c = 0; c < 4; c++) {
            float4 t = a4[c * 32];
            a[4*c+0] = t.x; a[4*c+1] = t.y; a[4*c+2] = t.z; a[4*c+3] = t.w;
            float4 u = s4[c * 32];
            sv[4*c+0] = u.x; sv[4*c+1] = u.y; sv[4*c+2] = u.z; sv[4*c+3] = u.w;
        }
        const float2 st = g_rowstat[row];

        float sd = 0.f;
#pragma unroll
        for (int i = 0; i < 16; i++) sd += __expf(a[i] - st.x) * sv[i];
#pragma unroll
        for (int o = 16; o; o >>= 1) sd += __shfl_xor_sync(0xffffffffu, sd, o);

        if (lane == 0) {
            float toe = sd * st.y;
            acc += fmaxf(toe, EPSF) * fmaxf(__logf(toe), EPSF);
        }
    }

    // this block's 64-element chunk of sim: consistency + second-order
    float cl = 0.f, so = 0.f;
    if (tid < 64) {
        float s = g_sim[blockIdx.x * 64 + tid];
        float l = __logf(s);
        cl = fmaxf(l, -100.f);
        so = fmaxf(s, EPSF) * fmaxf(l, EPSF);
    }

    // column reduction: blocks 0..511 each own one column of g_colpart
    float cs = 0.f;
    if (blockIdx.x < N) {
        for (int b2 = tid; b2 < BLOCKS1; b2 += 256)
            cs += g_colpart[(size_t)b2 * N + blockIdx.x];
    }

    __shared__ float sh[256];
    __shared__ float sw[8];
    if (lane == 0) sw[warp] = acc;

    float cl_sum = block_sum_256(cl, sh);
    float so_sum = block_sum_256(so, sh);
    float cs_sum = block_sum_256(cs, sh);

    if (tid == 0) {
        float t = 0.f;
#pragma unroll
        for (int w = 0; w < 8; w++) t += sw[w];
        g_thirdpart[blockIdx.x] = t;
        g_clpart[blockIdx.x] = cl_sum;
        g_sopart[blockIdx.x] = so_sum;
        if (blockIdx.x < N) g_colsum[blockIdx.x] = cs_sum;
    }

    // ---- last-block final combine ----
    __shared__ int s_last;
    __threadfence();
    if (tid == 0) s_last = (atomicAdd(&g_count, 1u) == BLOCKS2 - 1u) ? 1 : 0;
    __syncthreads();
    if (!s_last) return;
    __threadfence();

    float th = 0.f, clp = 0.f, sop = 0.f;
    for (int i = tid; i < BLOCKS2; i += 256) {
        th  += g_thirdpart[i];
        clp += g_clpart[i];
        sop += g_sopart[i];
    }
    float ent = 0.f;
    for (int i = tid; i < N; i += 256) {
        float p  = g_colsum[i] * (1.f / (float)B);
        float p_ = fmaxf(p, EPSF);
        ent += p_ * __logf(p_);
    }

    float th_sum  = block_sum_256(th, sh);
    float clp_sum = block_sum_256(clp, sh);
    float sop_sum = block_sum_256(sop, sh);
    float ent_sum = block_sum_256(ent, sh);

    if (tid == 0) {
        float consistency = -clp_sum * (1.f / (float)B);
        float entropy     = -ent_sum;
        float second      = sop_sum;
        float third       = th_sum * (1.f / (float)N);
        float total = consistency
                    - 2.0f * entropy
                    + (0.25f / (float)N) * second
                    - (0.5f / sqrtf((float)N)) * third;
        out[0] = total;
        out[1] = consistency;
        out[2] = entropy;
        out[3] = second;
        out[4] = third;
        g_count = 0;   // reset for next graph replay
    }
}

// ---------------------------------------------------------------------------
extern "C" void kernel_launch(void* const* d_in, const int* in_sizes, int n_in,
                              void* d_out, int out_size) {
    const float* A  = (const float*)d_in[0];   // anchors  [65536, 512]
    const float* Nb = (const float*)d_in[1];   // neighbors[65536, 512]
    float* out = (float*)d_out;

    pass1_kernel<<<BLOCKS1, 256>>>(A, Nb);
    pass2_kernel<<<BLOCKS2, 256>>>(A, out);
}

// round 10
// speedup vs baseline: 1.1575x; 1.1575x over previous
#include <cuda_runtime.h>
#include <math.h>

#define B 65536
#define N 512
#define EPSF 1e-8f
#define BLOCKS1 1024
#define BLOCKS2 1024
#define RPW 8   // rows per warp (8 warps/block)

// ---------------- scratch (device globals; no allocation allowed) ----------
__device__ __align__(16) float  g_sim[B];              // 256 KB
__device__ __align__(8)  float2 g_rowstat[B];          // 512 KB: (rowmax, 1/rowsum) of anchors
__device__ float g_colpart[BLOCKS1 * N];               // 2 MB: per-pass1-block column sums
__device__ float g_colsum[N];
__device__ float g_thirdpart[BLOCKS2];
__device__ float g_clpart[BLOCKS2];
__device__ float g_sopart[BLOCKS2];
__device__ unsigned int g_count = 0;

__device__ __forceinline__ float warp_max(float v) {
#pragma unroll
    for (int o = 16; o; o >>= 1) v = fmaxf(v, __shfl_xor_sync(0xffffffffu, v, o));
    return v;
}

// ---------------------------------------------------------------------------
// Pass 1: per-row softmax of anchors & neighbors, sim[row], rowstat[row],
// and per-block column partial sums of anchors_prob (register-accumulated).
// Software-pipelined: row r+1's loads issue before row r's compute.
// grid = 1024 blocks x 256 threads; 1 warp per row, 8 rows per warp.
// ---------------------------------------------------------------------------
__global__ void __launch_bounds__(256, 2) pass1_kernel(const float* __restrict__ A,
                                                       const float* __restrict__ Nb) {
    const int warp = threadIdx.x >> 5;
    const int lane = threadIdx.x & 31;
    const int base = (blockIdx.x * 8 + warp) * RPW;

    float4 colacc[4];
#pragma unroll
    for (int c = 0; c < 4; c++) colacc[c] = make_float4(0.f, 0.f, 0.f, 0.f);

    // prologue: load row 0
    float4 ca[4], cb[4];
    {
        const float4* a4 = reinterpret_cast<const float4*>(A  + (size_t)base * N) + lane;
        const float4* n4 = reinterpret_cast<const float4*>(Nb + (size_t)base * N) + lane;
#pragma unroll
        for (int c = 0; c < 4; c++) { ca[c] = a4[c * 32]; cb[c] = n4[c * 32]; }
    }

#pragma unroll
    for (int r = 0; r < RPW; r++) {
        const int row = base + r;

        // prefetch next row (issues before current row's compute)
        float4 na[4], nb4[4];
        if (r + 1 < RPW) {
            const float4* a4 = reinterpret_cast<const float4*>(A  + (size_t)(row + 1) * N) + lane;
            const float4* n4 = reinterpret_cast<const float4*>(Nb + (size_t)(row + 1) * N) + lane;
#pragma unroll
            for (int c = 0; c < 4; c++) { na[c] = a4[c * 32]; nb4[c] = n4[c * 32]; }
        }

        float ma = -1e30f, mn = -1e30f;
#pragma unroll
        for (int c = 0; c < 4; c++) {
            ma = fmaxf(ma, fmaxf(fmaxf(ca[c].x, ca[c].y), fmaxf(ca[c].z, ca[c].w)));
            mn = fmaxf(mn, fmaxf(fmaxf(cb[c].x, cb[c].y), fmaxf(cb[c].z, cb[c].w)));
        }
        ma = warp_max(ma);
        mn = warp_max(mn);

        float sa0 = 0.f, sa1 = 0.f, sb0 = 0.f, sb1 = 0.f, sd0 = 0.f, sd1 = 0.f;
        float4 ea[4];
#pragma unroll
        for (int c = 0; c < 4; c++) {
            ea[c].x = __expf(ca[c].x - ma); ea[c].y = __expf(ca[c].y - ma);
            ea[c].z = __expf(ca[c].z - ma); ea[c].w = __expf(ca[c].w - ma);
            float ex = __expf(cb[c].x - mn), ey = __expf(cb[c].y - mn);
            float ez = __expf(cb[c].z - mn), ew = __expf(cb[c].w - mn);
            sa0 += ea[c].x + ea[c].y;  sa1 += ea[c].z + ea[c].w;
            sb0 += ex + ey;            sb1 += ez + ew;
            sd0 += ea[c].x * ex + ea[c].y * ey;
            sd1 += ea[c].z * ez + ea[c].w * ew;
        }
        float sa = sa0 + sa1, sb = sb0 + sb1, sd = sd0 + sd1;
#pragma unroll
        for (int o = 16; o; o >>= 1) {
            sa += __shfl_xor_sync(0xffffffffu, sa, o);
            sb += __shfl_xor_sync(0xffffffffu, sb, o);
            sd += __shfl_xor_sync(0xffffffffu, sd, o);
        }

        const float inv = 1.f / sa;
        if (lane == 0) {
            g_sim[row] = sd / (sa * sb);
            g_rowstat[row] = make_float2(ma, inv);
        }
#pragma unroll
        for (int c = 0; c < 4; c++) {
            colacc[c].x += ea[c].x * inv; colacc[c].y += ea[c].y * inv;
            colacc[c].z += ea[c].z * inv; colacc[c].w += ea[c].w * inv;
        }

#pragma unroll
        for (int c = 0; c < 4; c++) { ca[c] = na[c]; cb[c] = nb4[c]; }
    }

    // combine per-warp register accumulators once
    __shared__ float scol[8][N];                 // 16 KB
#pragma unroll
    for (int c = 0; c < 4; c++)
        *reinterpret_cast<float4*>(&scol[warp][c * 128 + 4 * lane]) = colacc[c];
    __syncthreads();

    for (int col = threadIdx.x; col < N; col += 256) {
        float s = 0.f;
#pragma unroll
        for (int w = 0; w < 8; w++) s += scol[w][col];
        g_colpart[(size_t)blockIdx.x * N + col] = s;
    }
}

// ---------------------------------------------------------------------------
// Pass 2: third-order term using stored rowstats, software-pipelined,
// plus distributed reductions of sim (consistency/second-order) and colpart,
// plus final combine in the last-finishing block.
// grid = 1024 blocks x 256 threads.
// ---------------------------------------------------------------------------
__device__ __forceinline__ float block_sum_256(float v, float* sh) {
    const int tid = threadIdx.x;
    sh[tid] = v; __syncthreads();
#pragma unroll
    for (int st = 128; st > 0; st >>= 1) {
        if (tid < st) sh[tid] += sh[tid + st];
        __syncthreads();
    }
    float r = sh[0]; __syncthreads();
    return r;
}

__global__ void __launch_bounds__(256, 2) pass2_kernel(const float* __restrict__ A,
                                                       float* __restrict__ out) {
    const int warp = threadIdx.x >> 5;
    const int lane = threadIdx.x & 31;
    const int tid  = threadIdx.x;
    const int base = (blockIdx.x * 8 + warp) * RPW;

    // prologue: load row 0
    float4 ca[4], cs[4];
    float2 cst;
    {
        const float4* a4 = reinterpret_cast<const float4*>(A + (size_t)base * N) + lane;
        const float4* s4 = reinterpret_cast<const float4*>(g_sim + ((base & 127) << 9)) + lane;
#pragma unroll
        for (int c = 0; c < 4; c++) { ca[c] = a4[c * 32]; cs[c] = s4[c * 32]; }
        cst = g_rowstat[base];
    }

    float acc = 0.f;
#pragma unroll
    for (int r = 0; r < RPW; r++) {
        const int row = base + r;

        float4 na[4], ns[4];
        float2 nst;
        if (r + 1 < RPW) {
            const float4* a4 = reinterpret_cast<const float4*>(A + (size_t)(row + 1) * N) + lane;
            const float4* s4 = reinterpret_cast<const float4*>(g_sim + (((row + 1) & 127) << 9)) + lane;
#pragma unroll
            for (int c = 0; c < 4; c++) { na[c] = a4[c * 32]; ns[c] = s4[c * 32]; }
            nst = g_rowstat[row + 1];
        }

        float sd0 = 0.f, sd1 = 0.f;
#pragma unroll
        for (int c = 0; c < 4; c++) {
            sd0 += __expf(ca[c].x - cst.x) * cs[c].x + __expf(ca[c].y - cst.x) * cs[c].y;
            sd1 += __expf(ca[c].z - cst.x) * cs[c].z + __expf(ca[c].w - cst.x) * cs[c].w;
        }
        float sd = sd0 + sd1;
#pragma unroll
        for (int o = 16; o; o >>= 1) sd += __shfl_xor_sync(0xffffffffu, sd, o);

        if (lane == 0) {
            float toe = sd * cst.y;
            acc += fmaxf(toe, EPSF) * fmaxf(__logf(toe), EPSF);
        }

#pragma unroll
        for (int c = 0; c < 4; c++) { ca[c] = na[c]; cs[c] = ns[c]; }
        cst = nst;
    }

    // this block's 64-element chunk of sim: consistency + second-order
    float cl = 0.f, so = 0.f;
    if (tid < 64) {
        float s = g_sim[blockIdx.x * 64 + tid];
        float l = __logf(s);
        cl = fmaxf(l, -100.f);
        so = fmaxf(s, EPSF) * fmaxf(l, EPSF);
    }

    // column reduction: blocks 0..511 each own one column of g_colpart
    float cs2 = 0.f;
    if (blockIdx.x < N) {
        for (int b2 = tid; b2 < BLOCKS1; b2 += 256)
            cs2 += g_colpart[(size_t)b2 * N + blockIdx.x];
    }

    __shared__ float sh[256];
    __shared__ float sw[8];
    if (lane == 0) sw[warp] = acc;

    float cl_sum = block_sum_256(cl, sh);
    float so_sum = block_sum_256(so, sh);
    float cs_sum = block_sum_256(cs2, sh);

    if (tid == 0) {
        float t = 0.f;
#pragma unroll
        for (int w = 0; w < 8; w++) t += sw[w];
        g_thirdpart[blockIdx.x] = t;
        g_clpart[blockIdx.x] = cl_sum;
        g_sopart[blockIdx.x] = so_sum;
        if (blockIdx.x < N) g_colsum[blockIdx.x] = cs_sum;
    }

    // ---- last-block final combine ----
    __shared__ int s_last;
    __threadfence();
    if (tid == 0) s_last = (atomicAdd(&g_count, 1u) == BLOCKS2 - 1u) ? 1 : 0;
    __syncthreads();
    if (!s_last) return;
    __threadfence();

    float th = 0.f, clp = 0.f, sop = 0.f;
    for (int i = tid; i < BLOCKS2; i += 256) {
        th  += g_thirdpart[i];
        clp += g_clpart[i];
        sop += g_sopart[i];
    }
    float ent = 0.f;
    for (int i = tid; i < N; i += 256) {
        float p  = g_colsum[i] * (1.f / (float)B);
        float p_ = fmaxf(p, EPSF);
        ent += p_ * __logf(p_);
    }

    float th_sum  = block_sum_256(th, sh);
    float clp_sum = block_sum_256(clp, sh);
    float sop_sum = block_sum_256(sop, sh);
    float ent_sum = block_sum_256(ent, sh);

    if (tid == 0) {
        float consistency = -clp_sum * (1.f / (float)B);
        float entropy     = -ent_sum;
        float second      = sop_sum;
        float third       = th_sum * (1.f / (float)N);
        float total = consistency
                    - 2.0f * entropy
                    + (0.25f / (float)N) * second
                    - (0.5f / sqrtf((float)N)) * third;
        out[0] = total;
        out[1] = consistency;
        out[2] = entropy;
        out[3] = second;
        out[4] = third;
        g_count = 0;   // reset for next graph replay
    }
}

// ---------------------------------------------------------------------------
extern "C" void kernel_launch(void* const* d_in, const int* in_sizes, int n_in,
                              void* d_out, int out_size) {
    const float* A  = (const float*)d_in[0];   // anchors  [65536, 512]
    const float* Nb = (const float*)d_in[1];   // neighbors[65536, 512]
    float* out = (float*)d_out;

    pass1_kernel<<<BLOCKS1, 256>>>(A, Nb);
    pass2_kernel<<<BLOCKS2, 256>>>(A, out);
}

// round 13
// speedup vs baseline: 1.2787x; 1.1047x over previous
#include <cuda_runtime.h>
#include <cuda_fp16.h>
#include <math.h>

#define B 65536
#define N 512
#define EPSF 1e-8f
#define BLOCKS1 1024
#define BLOCKS2 1024
#define RPW 8   // rows per warp in pass1 (8 warps/block)

// ---------------- scratch (device globals; no allocation allowed) ----------
__device__ __align__(16) float  g_sim[B];              // 256 KB
__device__ __align__(16) __half g_E[(size_t)B * N];    // 64 MB: anchors_prob in fp16
__device__ float g_colpart[BLOCKS1 * N];               // 2 MB: per-pass1-block column sums
__device__ float g_colsum[N];
__device__ float g_thirdpart[BLOCKS2];
__device__ float g_clpart[BLOCKS2];
__device__ float g_sopart[BLOCKS2];
__device__ unsigned int g_count = 0;

__device__ __forceinline__ float warp_max(float v) {
#pragma unroll
    for (int o = 16; o; o >>= 1) v = fmaxf(v, __shfl_xor_sync(0xffffffffu, v, o));
    return v;
}

// ---------------------------------------------------------------------------
// Pass 1: per-row softmax of anchors & neighbors, sim[row], fp16 anchors_prob,
// and per-block column partial sums of anchors_prob (register-accumulated).
// Software-pipelined: row r+1's loads issue before row r's compute.
// grid = 1024 blocks x 256 threads; 1 warp per row, 8 rows per warp.
// ---------------------------------------------------------------------------
__global__ void __launch_bounds__(256, 2) pass1_kernel(const float* __restrict__ A,
                                                       const float* __restrict__ Nb) {
    const int warp = threadIdx.x >> 5;
    const int lane = threadIdx.x & 31;
    const int base = (blockIdx.x * 8 + warp) * RPW;

    float4 colacc[4];
#pragma unroll
    for (int c = 0; c < 4; c++) colacc[c] = make_float4(0.f, 0.f, 0.f, 0.f);

    // prologue: load row 0
    float4 ca[4], cb[4];
    {
        const float4* a4 = reinterpret_cast<const float4*>(A  + (size_t)base * N) + lane;
        const float4* n4 = reinterpret_cast<const float4*>(Nb + (size_t)base * N) + lane;
#pragma unroll
        for (int c = 0; c < 4; c++) { ca[c] = a4[c * 32]; cb[c] = n4[c * 32]; }
    }

#pragma unroll
    for (int r = 0; r < RPW; r++) {
        const int row = base + r;

        // prefetch next row (issues before current row's compute)
        float4 na[4], nb4[4];
        if (r + 1 < RPW) {
            const float4* a4 = reinterpret_cast<const float4*>(A  + (size_t)(row + 1) * N) + lane;
            const float4* n4 = reinterpret_cast<const float4*>(Nb + (size_t)(row + 1) * N) + lane;
#pragma unroll
            for (int c = 0; c < 4; c++) { na[c] = a4[c * 32]; nb4[c] = n4[c * 32]; }
        }

        float ma = -1e30f, mn = -1e30f;
#pragma unroll
        for (int c = 0; c < 4; c++) {
            ma = fmaxf(ma, fmaxf(fmaxf(ca[c].x, ca[c].y), fmaxf(ca[c].z, ca[c].w)));
            mn = fmaxf(mn, fmaxf(fmaxf(cb[c].x, cb[c].y), fmaxf(cb[c].z, cb[c].w)));
        }
        ma = warp_max(ma);
        mn = warp_max(mn);

        float sa0 = 0.f, sa1 = 0.f, sb0 = 0.f, sb1 = 0.f, sd0 = 0.f, sd1 = 0.f;
        float4 ea[4];
#pragma unroll
        for (int c = 0; c < 4; c++) {
            ea[c].x = __expf(ca[c].x - ma); ea[c].y = __expf(ca[c].y - ma);
            ea[c].z = __expf(ca[c].z - ma); ea[c].w = __expf(ca[c].w - ma);
            float ex = __expf(cb[c].x - mn), ey = __expf(cb[c].y - mn);
            float ez = __expf(cb[c].z - mn), ew = __expf(cb[c].w - mn);
            sa0 += ea[c].x + ea[c].y;  sa1 += ea[c].z + ea[c].w;
            sb0 += ex + ey;            sb1 += ez + ew;
            sd0 += ea[c].x * ex + ea[c].y * ey;
            sd1 += ea[c].z * ez + ea[c].w * ew;
        }
        float sa = sa0 + sa1, sb = sb0 + sb1, sd = sd0 + sd1;
#pragma unroll
        for (int o = 16; o; o >>= 1) {
            sa += __shfl_xor_sync(0xffffffffu, sa, o);
            sb += __shfl_xor_sync(0xffffffffu, sb, o);
            sd += __shfl_xor_sync(0xffffffffu, sd, o);
        }

        const float inv = 1.f / sa;
        if (lane == 0) g_sim[row] = sd / (sa * sb);

#pragma unroll
        for (int c = 0; c < 4; c++) {
            float px = ea[c].x * inv, py = ea[c].y * inv;
            float pz = ea[c].z * inv, pw = ea[c].w * inv;
            colacc[c].x += px; colacc[c].y += py;
            colacc[c].z += pz; colacc[c].w += pw;
            __half2 h0 = __floats2half2_rn(px, py);
            __half2 h1 = __floats2half2_rn(pz, pw);
            float2 pk = make_float2(__uint_as_float(*reinterpret_cast<unsigned int*>(&h0)),
                                    __uint_as_float(*reinterpret_cast<unsigned int*>(&h1)));
            __stcs(reinterpret_cast<float2*>(g_E + (size_t)row * N + c * 128 + 4 * lane), pk);
        }

#pragma unroll
        for (int c = 0; c < 4; c++) { ca[c] = na[c]; cb[c] = nb4[c]; }
    }

    // combine per-warp register accumulators once
    __shared__ float scol[8][N];                 // 16 KB
#pragma unroll
    for (int c = 0; c < 4; c++)
        *reinterpret_cast<float4*>(&scol[warp][c * 128 + 4 * lane]) = colacc[c];
    __syncthreads();

    for (int col = threadIdx.x; col < N; col += 256) {
        float s = 0.f;
#pragma unroll
        for (int w = 0; w < 8; w++) s += scol[w][col];
        g_colpart[(size_t)blockIdx.x * N + col] = s;
    }
}

// ---------------------------------------------------------------------------
// Pass 2: third-order term. Block (g, chunk) handles all rows with
// (row & 127) == g — they all share ONE 2 KB sim window, kept in registers.
// Per row: 2x LDG.128 of fp16 aprob + 16 FMAs + warp reduce. No MUFU, no A.
// Also: distributed reductions of sim (consistency/second-order) and colpart,
// plus final combine in the last-finishing block.
// grid = 1024 blocks x 256 threads.
// ---------------------------------------------------------------------------
__device__ __forceinline__ float block_sum_256(float v, float* sh) {
    const int tid = threadIdx.x;
    sh[tid] = v; __syncthreads();
#pragma unroll
    for (int st = 128; st > 0; st >>= 1) {
        if (tid < st) sh[tid] += sh[tid + st];
        __syncthreads();
    }
    float r = sh[0]; __syncthreads();
    return r;
}

__global__ void __launch_bounds__(256, 4) pass2_kernel(float* __restrict__ out) {
    const int warp = threadIdx.x >> 5;
    const int lane = threadIdx.x & 31;
    const int tid  = threadIdx.x;

    const int g     = blockIdx.x & 127;   // sim window id
    const int chunk = blockIdx.x >> 7;    // which 64 of the 512 rows sharing g

    // load the shared sim window into registers: cols lane*16 .. lane*16+15
    float4 w[4];
    {
        const float4* w4 = reinterpret_cast<const float4*>(g_sim + (g << 9)) + lane * 4;
#pragma unroll
        for (int k = 0; k < 4; k++) w[k] = w4[k];
    }

    const int kbase = chunk * 64 + warp * 8;   // k index; row = g + 128*k

    // prologue: load E for first row
    uint4 e0, e1;
    {
        const uint4* ep = reinterpret_cast<const uint4*>(
            g_E + ((size_t)(g + 128 * kbase)) * N + lane * 16);
        e0 = __ldcs(ep); e1 = __ldcs(ep + 1);
    }

    float acc = 0.f;
#pragma unroll
    for (int j = 0; j < 8; j++) {
        uint4 f0, f1;
        if (j + 1 < 8) {
            const uint4* ep = reinterpret_cast<const uint4*>(
                g_E + ((size_t)(g + 128 * (kbase + j + 1))) * N + lane * 16);
            f0 = __ldcs(ep); f1 = __ldcs(ep + 1);
        }

        float sd0 = 0.f, sd1 = 0.f;
        float2 p;
        p = __half22float2(*reinterpret_cast<__half2*>(&e0.x)); sd0 += p.x * w[0].x + p.y * w[0].y;
        p = __half22float2(*reinterpret_cast<__half2*>(&e0.y)); sd0 += p.x * w[0].z + p.y * w[0].w;
        p = __half22float2(*reinterpret_cast<__half2*>(&e0.z)); sd1 += p.x * w[1].x + p.y * w[1].y;
        p = __half22float2(*reinterpret_cast<__half2*>(&e0.w)); sd1 += p.x * w[1].z + p.y * w[1].w;
        p = __half22float2(*reinterpret_cast<__half2*>(&e1.x)); sd0 += p.x * w[2].x + p.y * w[2].y;
        p = __half22float2(*reinterpret_cast<__half2*>(&e1.y)); sd0 += p.x * w[2].z + p.y * w[2].w;
        p = __half22float2(*reinterpret_cast<__half2*>(&e1.z)); sd1 += p.x * w[3].x + p.y * w[3].y;
        p = __half22float2(*reinterpret_cast<__half2*>(&e1.w)); sd1 += p.x * w[3].z + p.y * w[3].w;

        float sdv = sd0 + sd1;
#pragma unroll
        for (int o = 16; o; o >>= 1) sdv += __shfl_xor_sync(0xffffffffu, sdv, o);

        if (lane == 0) {
            float toe = sdv;   // already normalized (E = aprob)
            acc += fmaxf(toe, EPSF) * fmaxf(__logf(toe), EPSF);
        }

        e0 = f0; e1 = f1;
    }

    // this block's 64-element chunk of sim: consistency + second-order
    float cl = 0.f, so = 0.f;
    if (tid < 64) {
        float s = g_sim[blockIdx.x * 64 + tid];
        float l = __logf(s);
        cl = fmaxf(l, -100.f);
        so = fmaxf(s, EPSF) * fmaxf(l, EPSF);
    }

    // column reduction: blocks 0..511 each own one column of g_colpart
    float cs2 = 0.f;
    if (blockIdx.x < N) {
        for (int b2 = tid; b2 < BLOCKS1; b2 += 256)
            cs2 += g_colpart[(size_t)b2 * N + blockIdx.x];
    }

    __shared__ float sh[256];
    __shared__ float sw[8];
    if (lane == 0) sw[warp] = acc;

    float cl_sum = block_sum_256(cl, sh);
    float so_sum = block_sum_256(so, sh);
    float cs_sum = block_sum_256(cs2, sh);

    if (tid == 0) {
        float t = 0.f;
#pragma unroll
        for (int w2 = 0; w2 < 8; w2++) t += sw[w2];
        g_thirdpart[blockIdx.x] = t;
        g_clpart[blockIdx.x] = cl_sum;
        g_sopart[blockIdx.x] = so_sum;
        if (blockIdx.x < N) g_colsum[blockIdx.x] = cs_sum;
    }

    // ---- last-block final combine ----
    __shared__ int s_last;
    __threadfence();
    if (tid == 0) s_last = (atomicAdd(&g_count, 1u) == BLOCKS2 - 1u) ? 1 : 0;
    __syncthreads();
    if (!s_last) return;
    __threadfence();

    float th = 0.f, clp = 0.f, sop = 0.f;
    for (int i = tid; i < BLOCKS2; i += 256) {
        th  += g_thirdpart[i];
        clp += g_clpart[i];
        sop += g_sopart[i];
    }
    float ent = 0.f;
    for (int i = tid; i < N; i += 256) {
        float pv  = g_colsum[i] * (1.f / (float)B);
        float p_  = fmaxf(pv, EPSF);
        ent += p_ * __logf(p_);
    }

    float th_sum  = block_sum_256(th, sh);
    float clp_sum = block_sum_256(clp, sh);
    float sop_sum = block_sum_256(sop, sh);
    float ent_sum = block_sum_256(ent, sh);

    if (tid == 0) {
        float consistency = -clp_sum * (1.f / (float)B);
        float entropy     = -ent_sum;
        float second      = sop_sum;
        float third       = th_sum * (1.f / (float)N);
        float total = consistency
                    - 2.0f * entropy
                    + (0.25f / (float)N) * second
                    - (0.5f / sqrtf((float)N)) * third;
        out[0] = total;
        out[1] = consistency;
        out[2] = entropy;
        out[3] = second;
        out[4] = third;
        g_count = 0;   // reset for next graph replay
    }
}

// ---------------------------------------------------------------------------
extern "C" void kernel_launch(void* const* d_in, const int* in_sizes, int n_in,
                              void* d_out, int out_size) {
    const float* A  = (const float*)d_in[0];   // anchors  [65536, 512]
    const float* Nb = (const float*)d_in[1];   // neighbors[65536, 512]
    float* out = (float*)d_out;

    pass1_kernel<<<BLOCKS1, 256>>>(A, Nb);
    pass2_kernel<<<BLOCKS2, 256>>>(out);
}

// round 14
// speedup vs baseline: 1.3251x; 1.0363x over previous
#include <cuda_runtime.h>
#include <cuda_fp16.h>
#include <math.h>

#define B 65536
#define N 512
#define EPSF 1e-8f
#define BLOCKS1 1024
#define BLOCKS2 1024
#define RPW 8   // rows per warp in pass1 (8 warps/block)

// ---------------- scratch (device globals; no allocation allowed) ----------
__device__ __align__(16) float  g_sim[B];              // 256 KB
__device__ __align__(16) __half g_E[(size_t)B * N];    // 64 MB: anchors_prob fp16 (L2-resident)
__device__ float g_colpart[BLOCKS1 * N];               // 2 MB
__device__ float g_colsum[N];
__device__ float g_thirdpart[BLOCKS2];
__device__ float g_clpart[BLOCKS2];
__device__ float g_sopart[BLOCKS2];
__device__ unsigned int g_count = 0;

__device__ __forceinline__ float warp_max(float v) {
#pragma unroll
    for (int o = 16; o; o >>= 1) v = fmaxf(v, __shfl_xor_sync(0xffffffffu, v, o));
    return v;
}

// ---------------------------------------------------------------------------
// Pass 1: per-row softmax of anchors & neighbors, sim[row], fp16 anchors_prob,
// and per-block column partial sums. A/Nb read with __ldcs (streaming — keep
// out of L2); E written with default policy (stays in L2 for pass2).
// ---------------------------------------------------------------------------
__global__ void __launch_bounds__(256, 2) pass1_kernel(const float* __restrict__ A,
                                                       const float* __restrict__ Nb) {
    const int warp = threadIdx.x >> 5;
    const int lane = threadIdx.x & 31;
    const int base = (blockIdx.x * 8 + warp) * RPW;

    float4 colacc[4];
#pragma unroll
    for (int c = 0; c < 4; c++) colacc[c] = make_float4(0.f, 0.f, 0.f, 0.f);

    // prologue: load row 0 (streaming)
    float4 ca[4], cb[4];
    {
        const float4* a4 = reinterpret_cast<const float4*>(A  + (size_t)base * N) + lane;
        const float4* n4 = reinterpret_cast<const float4*>(Nb + (size_t)base * N) + lane;
#pragma unroll
        for (int c = 0; c < 4; c++) { ca[c] = __ldcs(&a4[c * 32]); cb[c] = __ldcs(&n4[c * 32]); }
    }

#pragma unroll
    for (int r = 0; r < RPW; r++) {
        const int row = base + r;

        // prefetch next row
        float4 na[4], nb4[4];
        if (r + 1 < RPW) {
            const float4* a4 = reinterpret_cast<const float4*>(A  + (size_t)(row + 1) * N) + lane;
            const float4* n4 = reinterpret_cast<const float4*>(Nb + (size_t)(row + 1) * N) + lane;
#pragma unroll
            for (int c = 0; c < 4; c++) { na[c] = __ldcs(&a4[c * 32]); nb4[c] = __ldcs(&n4[c * 32]); }
        }

        float ma = -1e30f, mn = -1e30f;
#pragma unroll
        for (int c = 0; c < 4; c++) {
            ma = fmaxf(ma, fmaxf(fmaxf(ca[c].x, ca[c].y), fmaxf(ca[c].z, ca[c].w)));
            mn = fmaxf(mn, fmaxf(fmaxf(cb[c].x, cb[c].y), fmaxf(cb[c].z, cb[c].w)));
        }
        ma = warp_max(ma);
        mn = warp_max(mn);

        float sa0 = 0.f, sa1 = 0.f, sb0 = 0.f, sb1 = 0.f, sd0 = 0.f, sd1 = 0.f;
        float4 ea[4];
#pragma unroll
        for (int c = 0; c < 4; c++) {
            ea[c].x = __expf(ca[c].x - ma); ea[c].y = __expf(ca[c].y - ma);
            ea[c].z = __expf(ca[c].z - ma); ea[c].w = __expf(ca[c].w - ma);
            float ex = __expf(cb[c].x - mn), ey = __expf(cb[c].y - mn);
            float ez = __expf(cb[c].z - mn), ew = __expf(cb[c].w - mn);
            sa0 += ea[c].x + ea[c].y;  sa1 += ea[c].z + ea[c].w;
            sb0 += ex + ey;            sb1 += ez + ew;
            sd0 += ea[c].x * ex + ea[c].y * ey;
            sd1 += ea[c].z * ez + ea[c].w * ew;
        }
        float sa = sa0 + sa1, sb = sb0 + sb1, sd = sd0 + sd1;
#pragma unroll
        for (int o = 16; o; o >>= 1) {
            sa += __shfl_xor_sync(0xffffffffu, sa, o);
            sb += __shfl_xor_sync(0xffffffffu, sb, o);
            sd += __shfl_xor_sync(0xffffffffu, sd, o);
        }

        const float inv = 1.f / sa;
        if (lane == 0) g_sim[row] = sd / (sa * sb);

#pragma unroll
        for (int c = 0; c < 4; c++) {
            float px = ea[c].x * inv, py = ea[c].y * inv;
            float pz = ea[c].z * inv, pw = ea[c].w * inv;
            colacc[c].x += px; colacc[c].y += py;
            colacc[c].z += pz; colacc[c].w += pw;
            __half2 h0 = __floats2half2_rn(px, py);
            __half2 h1 = __floats2half2_rn(pz, pw);
            float2 pk = make_float2(__uint_as_float(*reinterpret_cast<unsigned int*>(&h0)),
                                    __uint_as_float(*reinterpret_cast<unsigned int*>(&h1)));
            // default store policy: keep E resident in L2 for pass2
            *reinterpret_cast<float2*>(g_E + (size_t)row * N + c * 128 + 4 * lane) = pk;
        }

#pragma unroll
        for (int c = 0; c < 4; c++) { ca[c] = na[c]; cb[c] = nb4[c]; }
    }

    // combine per-warp register accumulators once
    __shared__ float scol[8][N];                 // 16 KB
#pragma unroll
    for (int c = 0; c < 4; c++)
        *reinterpret_cast<float4*>(&scol[warp][c * 128 + 4 * lane]) = colacc[c];
    __syncthreads();

    for (int col = threadIdx.x; col < N; col += 256) {
        float s = 0.f;
#pragma unroll
        for (int w = 0; w < 8; w++) s += scol[w][col];
        g_colpart[(size_t)blockIdx.x * N + col] = s;
    }
}

// ---------------------------------------------------------------------------
// Pass 2: third-order term. Block (g, chunk): rows row = g + 128*k share ONE
// 2 KB sim window kept in registers. Rows processed in PAIRS (two independent
// FMA + reduce chains), next pair prefetched. E reads hit L2.
// ---------------------------------------------------------------------------
__device__ __forceinline__ float block_sum_256(float v, float* sh) {
    const int tid = threadIdx.x;
    sh[tid] = v; __syncthreads();
#pragma unroll
    for (int st = 128; st > 0; st >>= 1) {
        if (tid < st) sh[tid] += sh[tid + st];
        __syncthreads();
    }
    float r = sh[0]; __syncthreads();
    return r;
}

__device__ __forceinline__ float row_dot(const uint4& e0, const uint4& e1, const float4* w) {
    float s0 = 0.f, s1 = 0.f;
    float2 p;
    p = __half22float2(*reinterpret_cast<const __half2*>(&e0.x)); s0 += p.x * w[0].x + p.y * w[0].y;
    p = __half22float2(*reinterpret_cast<const __half2*>(&e0.y)); s0 += p.x * w[0].z + p.y * w[0].w;
    p = __half22float2(*reinterpret_cast<const __half2*>(&e0.z)); s1 += p.x * w[1].x + p.y * w[1].y;
    p = __half22float2(*reinterpret_cast<const __half2*>(&e0.w)); s1 += p.x * w[1].z + p.y * w[1].w;
    p = __half22float2(*reinterpret_cast<const __half2*>(&e1.x)); s0 += p.x * w[2].x + p.y * w[2].y;
    p = __half22float2(*reinterpret_cast<const __half2*>(&e1.y)); s0 += p.x * w[2].z + p.y * w[2].w;
    p = __half22float2(*reinterpret_cast<const __half2*>(&e1.z)); s1 += p.x * w[3].x + p.y * w[3].y;
    p = __half22float2(*reinterpret_cast<const __half2*>(&e1.w)); s1 += p.x * w[3].z + p.y * w[3].w;
    return s0 + s1;
}

__global__ void __launch_bounds__(256, 3) pass2_kernel(float* __restrict__ out) {
    const int warp = threadIdx.x >> 5;
    const int lane = threadIdx.x & 31;
    const int tid  = threadIdx.x;

    const int g     = blockIdx.x & 127;   // sim window id
    const int chunk = blockIdx.x >> 7;    // which 64 of the 512 rows sharing g

    // load the shared sim window into registers: cols lane*16 .. lane*16+15
    float4 w[4];
    {
        const float4* w4 = reinterpret_cast<const float4*>(g_sim + (g << 9)) + lane * 4;
#pragma unroll
        for (int k = 0; k < 4; k++) w[k] = w4[k];
    }

    const int kbase = chunk * 64 + warp * 8;   // k index; row = g + 128*k

    // prologue: load E for first pair of rows
    uint4 c00, c01, c10, c11;
    {
        const uint4* p0 = reinterpret_cast<const uint4*>(
            g_E + ((size_t)(g + 128 * kbase)) * N + lane * 16);
        const uint4* p1 = reinterpret_cast<const uint4*>(
            g_E + ((size_t)(g + 128 * (kbase + 1))) * N + lane * 16);
        c00 = p0[0]; c01 = p0[1];
        c10 = p1[0]; c11 = p1[1];
    }

    float acc = 0.f;
#pragma unroll
    for (int j = 0; j < 8; j += 2) {
        uint4 n00, n01, n10, n11;
        if (j + 2 < 8) {
            const uint4* p0 = reinterpret_cast<const uint4*>(
                g_E + ((size_t)(g + 128 * (kbase + j + 2))) * N + lane * 16);
            const uint4* p1 = reinterpret_cast<const uint4*>(
                g_E + ((size_t)(g + 128 * (kbase + j + 3))) * N + lane * 16);
            n00 = p0[0]; n01 = p0[1];
            n10 = p1[0]; n11 = p1[1];
        }

        float sA = row_dot(c00, c01, w);
        float sB = row_dot(c10, c11, w);
#pragma unroll
        for (int o = 16; o; o >>= 1) {
            sA += __shfl_xor_sync(0xffffffffu, sA, o);
            sB += __shfl_xor_sync(0xffffffffu, sB, o);
        }

        if (lane == 0) {
            acc += fmaxf(sA, EPSF) * fmaxf(__logf(sA), EPSF);
            acc += fmaxf(sB, EPSF) * fmaxf(__logf(sB), EPSF);
        }

        c00 = n00; c01 = n01; c10 = n10; c11 = n11;
    }

    // this block's 64-element chunk of sim: consistency + second-order
    float cl = 0.f, so = 0.f;
    if (tid < 64) {
        float s = g_sim[blockIdx.x * 64 + tid];
        float l = __logf(s);
        cl = fmaxf(l, -100.f);
        so = fmaxf(s, EPSF) * fmaxf(l, EPSF);
    }

    // column reduction: blocks 0..511 each own one column of g_colpart
    float cs2 = 0.f;
    if (blockIdx.x < N) {
        for (int b2 = tid; b2 < BLOCKS1; b2 += 256)
            cs2 += g_colpart[(size_t)b2 * N + blockIdx.x];
    }

    __shared__ float sh[256];
    __shared__ float sw[8];
    if (lane == 0) sw[warp] = acc;

    float cl_sum = block_sum_256(cl, sh);
    float so_sum = block_sum_256(so, sh);
    float cs_sum = block_sum_256(cs2, sh);

    if (tid == 0) {
        float t = 0.f;
#pragma unroll
        for (int w2 = 0; w2 < 8; w2++) t += sw[w2];
        g_thirdpart[blockIdx.x] = t;
        g_clpart[blockIdx.x] = cl_sum;
        g_sopart[blockIdx.x] = so_sum;
        if (blockIdx.x < N) g_colsum[blockIdx.x] = cs_sum;
    }

    // ---- last-block final combine ----
    __shared__ int s_last;
    __threadfence();
    if (tid == 0) s_last = (atomicAdd(&g_count, 1u) == BLOCKS2 - 1u) ? 1 : 0;
    __syncthreads();
    if (!s_last) return;
    __threadfence();

    float th = 0.f, clp = 0.f, sop = 0.f;
    for (int i = tid; i < BLOCKS2; i += 256) {
        th  += g_thirdpart[i];
        clp += g_clpart[i];
        sop += g_sopart[i];
    }
    float ent = 0.f;
    for (int i = tid; i < N; i += 256) {
        float pv  = g_colsum[i] * (1.f / (float)B);
        float p_  = fmaxf(pv, EPSF);
        ent += p_ * __logf(p_);
    }

    float th_sum  = block_sum_256(th, sh);
    float clp_sum = block_sum_256(clp, sh);
    float sop_sum = block_sum_256(sop, sh);
    float ent_sum = block_sum_256(ent, sh);

    if (tid == 0) {
        float consistency = -clp_sum * (1.f / (float)B);
        float entropy     = -ent_sum;
        float second      = sop_sum;
        float third       = th_sum * (1.f / (float)N);
        float total = consistency
                    - 2.0f * entropy
                    + (0.25f / (float)N) * second
                    - (0.5f / sqrtf((float)N)) * third;
        out[0] = total;
        out[1] = consistency;
        out[2] = entropy;
        out[3] = second;
        out[4] = third;
        g_count = 0;   // reset for next graph replay
    }
}

// ---------------------------------------------------------------------------
extern "C" void kernel_launch(void* const* d_in, const int* in_sizes, int n_in,
                              void* d_out, int out_size) {
    const float* A  = (const float*)d_in[0];   // anchors  [65536, 512]
    const float* Nb = (const float*)d_in[1];   // neighbors[65536, 512]
    float* out = (float*)d_out;

    pass1_kernel<<<BLOCKS1, 256>>>(A, Nb);
    pass2_kernel<<<BLOCKS2, 256>>>(out);
}